// round 4
// baseline (speedup 1.0000x reference)
#include <cuda_runtime.h>

// LSTM scan: T=2048, B=4096, IN_S=1, H=20, OUT_S=1, no biases.
// Round 4: small independent barrier groups. BPB=4 batches/block, TPB=80,
// 1024 blocks at 7 blocks/SM -> 7 dephased barrier groups per SM (lockstep
// fix). Gate-pair fp32x2 math (80 weight regs), split accumulators to halve
// the dependent-FMA chain, pow2 index math.

#define TSTEPS 2048
#define BATCH  4096
#define H      20
#define BPB    4             // batch elements per block (pow2!)
#define TPB    (BPB * H)     // 80 threads
#define CHUNK  64
#define NBLK   (BATCH / BPB) // 1024 blocks

union F2U { float2 f2; unsigned long long u; };

__device__ __forceinline__ float2 ffma2(float2 a, float2 b, float2 c) {
    F2U A, B, C, D; A.f2 = a; B.f2 = b; C.f2 = c;
    asm("fma.rn.f32x2 %0, %1, %2, %3;" : "=l"(D.u) : "l"(A.u), "l"(B.u), "l"(C.u));
    return D.f2;
}
__device__ __forceinline__ float2 fmul2(float2 a, float2 b) {
    F2U A, B, D; A.f2 = a; B.f2 = b;
    asm("mul.rn.f32x2 %0, %1, %2;" : "=l"(D.u) : "l"(A.u), "l"(B.u));
    return D.f2;
}
__device__ __forceinline__ float2 fadd2(float2 a, float2 b) {
    F2U A, B, D; A.f2 = a; B.f2 = b;
    asm("add.rn.f32x2 %0, %1, %2;" : "=l"(D.u) : "l"(A.u), "l"(B.u));
    return D.f2;
}

__device__ __forceinline__ float sigf(float x) {
    return __fdividef(1.0f, 1.0f + __expf(-x));
}
__device__ __forceinline__ float tanh_f(float x) {
    return 1.0f - __fdividef(2.0f, __expf(2.0f * x) + 1.0f);
}

__global__ void __launch_bounds__(TPB, 7)
lstm_scan_kernel(const float* __restrict__ u,     // [T, B, 1]
                 const float* __restrict__ Wih,   // [80, 1]
                 const float* __restrict__ Whh,   // [80, 20]
                 const float* __restrict__ Wout,  // [1, 20]
                 float* __restrict__ out)         // [T, B, 1]
{
    // h as duplicated pairs: h_sh[buf][b][j] = (h_j, h_j); float4 read yields
    // two ready fma.rn.f32x2 multipliers.
    __shared__ __align__(16) float2 h_sh[2][BPB][H];
    __shared__ float u_sh[CHUNK][BPB];
    __shared__ float y_sh[CHUNK][BPB];
    __shared__ float wout_sh[H];

    const int tid = threadIdx.x;
    const int bl  = tid / H;      // local batch 0..3
    const int k   = tid % H;      // hidden index 0..19
    const int b0  = blockIdx.x * BPB;

    // Gate-pair packed weights: 80 float regs total.
    float2 wif[H];   // (W_i[k][j], W_f[k][j])
    float2 wgo[H];   // (W_g[k][j], W_o[k][j])
#pragma unroll
    for (int j = 0; j < H; j++) {
        wif[j] = make_float2(Whh[k * H + j],           Whh[(H + k) * H + j]);
        wgo[j] = make_float2(Whh[(2 * H + k) * H + j], Whh[(3 * H + k) * H + j]);
    }
    const float2 wih_if = make_float2(Wih[k],         Wih[H + k]);
    const float2 wih_go = make_float2(Wih[2 * H + k], Wih[3 * H + k]);
    if (tid < H) wout_sh[tid] = Wout[tid];

    h_sh[0][bl][k] = make_float2(0.0f, 0.0f);
    float c = 0.0f;
    int pb = 0;

#pragma unroll 1
    for (int tc = 0; tc < TSTEPS / CHUNK; tc++) {
        __syncthreads();  // prev chunk y_sh complete; u_sh reads done

        if (tc > 0) {
            const int t0p = (tc - 1) * CHUNK;
#pragma unroll 1
            for (int e = tid; e < CHUNK * BPB; e += TPB) {
                const int r = e >> 2, cc = e & 3;
                out[(t0p + r) * BATCH + b0 + cc] = y_sh[r][cc];
            }
        }
        {
            const int t0 = tc * CHUNK;
#pragma unroll 1
            for (int e = tid; e < CHUNK * BPB; e += TPB) {
                const int r = e >> 2, cc = e & 3;
                u_sh[r][cc] = u[(t0 + r) * BATCH + b0 + cc];
            }
        }
        __syncthreads();

#pragma unroll 1
        for (int tt = 0; tt < CHUNK; tt++) {
            const float x = u_sh[tt][bl];
            const float2 x2 = make_float2(x, x);

            // Split accumulators: halve dependent-FMA chain depth.
            float2 aif0 = fmul2(x2, wih_if);
            float2 ago0 = fmul2(x2, wih_go);
            float2 aif1 = make_float2(0.0f, 0.0f);
            float2 ago1 = make_float2(0.0f, 0.0f);

            const float4* hv4 = reinterpret_cast<const float4*>(&h_sh[pb][bl][0]);
#pragma unroll
            for (int q = 0; q < H / 2; q += 2) {
                float4 v0 = hv4[q];          // dup pairs j=2q, 2q+1
                float4 v1 = hv4[q + 1];      // dup pairs j=2q+2, 2q+3
                float2 p00 = make_float2(v0.x, v0.y);
                float2 p01 = make_float2(v0.z, v0.w);
                float2 p10 = make_float2(v1.x, v1.y);
                float2 p11 = make_float2(v1.z, v1.w);
                aif0 = ffma2(p00, wif[2 * q], aif0);
                ago0 = ffma2(p00, wgo[2 * q], ago0);
                aif1 = ffma2(p01, wif[2 * q + 1], aif1);
                ago1 = ffma2(p01, wgo[2 * q + 1], ago1);
                aif0 = ffma2(p10, wif[2 * q + 2], aif0);
                ago0 = ffma2(p10, wgo[2 * q + 2], ago0);
                aif1 = ffma2(p11, wif[2 * q + 3], aif1);
                ago1 = ffma2(p11, wgo[2 * q + 3], ago1);
            }
            const float2 aif = fadd2(aif0, aif1);
            const float2 ago = fadd2(ago0, ago1);

            const float ig = sigf(aif.x);
            const float fg = sigf(aif.y);
            const float gg = tanh_f(ago.x);
            const float og = sigf(ago.y);
            c = fmaf(fg, c, ig * gg);
            const float h = og * tanh_f(c);

            h_sh[pb ^ 1][bl][k] = make_float2(h, h);
            __syncthreads();

            if (k == 0) {
                const float4* hv = reinterpret_cast<const float4*>(&h_sh[pb ^ 1][bl][0]);
                float y = 0.0f;
#pragma unroll
                for (int q = 0; q < H / 2; q++) {
                    float4 v = hv[q];
                    y = fmaf(v.x, wout_sh[2 * q], y);
                    y = fmaf(v.z, wout_sh[2 * q + 1], y);
                }
                y_sh[tt][bl] = y;
            }
            pb ^= 1;
        }
    }

    __syncthreads();
    {
        const int t0p = (TSTEPS / CHUNK - 1) * CHUNK;
#pragma unroll 1
        for (int e = tid; e < CHUNK * BPB; e += TPB) {
            const int r = e >> 2, cc = e & 3;
            out[(t0p + r) * BATCH + b0 + cc] = y_sh[r][cc];
        }
    }
}

extern "C" void kernel_launch(void* const* d_in, const int* in_sizes, int n_in,
                              void* d_out, int out_size) {
    const float* u    = (const float*)d_in[0];  // [2048, 4096, 1]
    const float* Wih  = (const float*)d_in[1];  // [80, 1]
    const float* Whh  = (const float*)d_in[2];  // [80, 20]
    const float* Wout = (const float*)d_in[3];  // [1, 20]
    float* out = (float*)d_out;                 // [2048, 4096, 1]

    lstm_scan_kernel<<<NBLK, TPB>>>(u, Wih, Whh, Wout, out);
}

// round 6
// speedup vs baseline: 1.7544x; 1.7544x over previous
#include <cuda_runtime.h>

// LSTM scan: T=2048, B=4096, IN_S=1, H=20, OUT_S=1, no biases.
// Round 5: revert to R1's scalar math (FFMA rt=2; f32x2/FFMA2 measured at
// half issue rate — no gain, extra LDS). Geometry fixed for ONE balanced
// wave: BPB=14, TPB=280, 293 blocks at 2 blocks/SM (296 slots).
// Thread = (batch, k): 4 gate dots of length 20 with weights in registers,
// h exchanged via double-buffered SMEM, one __syncthreads per step.

#define TSTEPS 2048
#define BATCH  4096
#define H      20
#define BPB    14            // batch elements per block
#define TPB    (BPB * H)     // 280 threads
#define CHUNK  64
#define NBLK   ((BATCH + BPB - 1) / BPB)  // 293 blocks

__device__ __forceinline__ float sigf(float x) {
    return __fdividef(1.0f, 1.0f + __expf(-x));
}
__device__ __forceinline__ float tanh_f(float x) {
    return 1.0f - __fdividef(2.0f, __expf(2.0f * x) + 1.0f);
}

__global__ void __launch_bounds__(TPB, 2)
lstm_scan_kernel(const float* __restrict__ u,     // [T, B, 1]
                 const float* __restrict__ Wih,   // [80, 1]
                 const float* __restrict__ Whh,   // [80, 20]
                 const float* __restrict__ Wout,  // [1, 20]
                 float* __restrict__ out)         // [T, B, 1]
{
    __shared__ __align__(16) float h_sh[2][BPB][H];   // double-buffered hidden
    __shared__ float u_sh[CHUNK][BPB];
    __shared__ float y_sh[CHUNK][BPB];
    __shared__ float wout_sh[H];

    const int tid = threadIdx.x;
    const int bl  = tid / H;     // local batch index 0..13
    const int k   = tid % H;     // hidden index 0..19
    const int b0  = blockIdx.x * BPB;

    // Per-thread weights: rows (g*20 + k) of W_hh for g = 0..3  (80 regs)
    float w[4][H];
    float wih[4];
#pragma unroll
    for (int g = 0; g < 4; g++) {
        wih[g] = Wih[g * H + k];
#pragma unroll
        for (int j = 0; j < H; j++)
            w[g][j] = Whh[(g * H + k) * H + j];
    }
    if (tid < H) wout_sh[tid] = Wout[tid];

    h_sh[0][bl][k] = 0.0f;   // h0 = 0
    float c = 0.0f;          // c0 = 0
    int pb = 0;              // buffer holding h_{t-1}

#pragma unroll 1
    for (int tc = 0; tc < TSTEPS / CHUNK; tc++) {
        __syncthreads();  // prev chunk's y_sh writes complete; u_sh reads done

        // Flush y of previous chunk
        if (tc > 0) {
            const int t0p = (tc - 1) * CHUNK;
#pragma unroll 1
            for (int e = tid; e < CHUNK * BPB; e += TPB) {
                const int r = e / BPB, cc = e % BPB;
                if (b0 + cc < BATCH)
                    out[(t0p + r) * BATCH + b0 + cc] = y_sh[r][cc];
            }
        }
        // Stage this chunk of u into SMEM
        {
            const int t0 = tc * CHUNK;
#pragma unroll 1
            for (int e = tid; e < CHUNK * BPB; e += TPB) {
                const int r = e / BPB, cc = e % BPB;
                u_sh[r][cc] = (b0 + cc < BATCH) ? u[(t0 + r) * BATCH + b0 + cc]
                                                : 0.0f;
            }
        }
        __syncthreads();

#pragma unroll 1
        for (int tt = 0; tt < CHUNK; tt++) {
            // Load h_{t-1} for my batch element (5x LDS128, broadcast)
            float hv[H];
#pragma unroll
            for (int q = 0; q < H / 4; q++) {
                float4 v = *reinterpret_cast<const float4*>(&h_sh[pb][bl][q * 4]);
                hv[q * 4 + 0] = v.x;
                hv[q * 4 + 1] = v.y;
                hv[q * 4 + 2] = v.z;
                hv[q * 4 + 3] = v.w;
            }
            const float x = u_sh[tt][bl];

            float ai = x * wih[0];
            float af = x * wih[1];
            float ag = x * wih[2];
            float ao = x * wih[3];
#pragma unroll
            for (int j = 0; j < H; j++) {
                ai = fmaf(hv[j], w[0][j], ai);
                af = fmaf(hv[j], w[1][j], af);
                ag = fmaf(hv[j], w[2][j], ag);
                ao = fmaf(hv[j], w[3][j], ao);
            }
            const float ig = sigf(ai);
            const float fg = sigf(af);
            const float gg = tanh_f(ag);
            const float og = sigf(ao);
            c = fmaf(fg, c, ig * gg);
            const float h = og * tanh_f(c);

            h_sh[pb ^ 1][bl][k] = h;
            __syncthreads();

            // One thread per batch element computes y_t = h_t . w_out
            if (k == 0) {
                float y = 0.0f;
#pragma unroll
                for (int j = 0; j < H; j++)
                    y = fmaf(h_sh[pb ^ 1][bl][j], wout_sh[j], y);
                y_sh[tt][bl] = y;
            }
            pb ^= 1;
        }
    }

    // Final chunk flush
    __syncthreads();
    {
        const int t0p = (TSTEPS / CHUNK - 1) * CHUNK;
#pragma unroll 1
        for (int e = tid; e < CHUNK * BPB; e += TPB) {
            const int r = e / BPB, cc = e % BPB;
            if (b0 + cc < BATCH)
                out[(t0p + r) * BATCH + b0 + cc] = y_sh[r][cc];
        }
    }
}

extern "C" void kernel_launch(void* const* d_in, const int* in_sizes, int n_in,
                              void* d_out, int out_size) {
    const float* u    = (const float*)d_in[0];  // [2048, 4096, 1]
    const float* Wih  = (const float*)d_in[1];  // [80, 1]
    const float* Whh  = (const float*)d_in[2];  // [80, 20]
    const float* Wout = (const float*)d_in[3];  // [1, 20]
    float* out = (float*)d_out;                 // [2048, 4096, 1]

    lstm_scan_kernel<<<NBLK, TPB>>>(u, Wih, Whh, Wout, out);
}

// round 7
// speedup vs baseline: 2.1947x; 1.2509x over previous
#include <cuda_runtime.h>

// LSTM scan: T=2048, B=4096, IN_S=1, H=20, OUT_S=1, no biases.
// Round 6: warp-autonomous blocks. One warp = one block = 2 batch elements,
// 16 lanes each. Lane j computes gate rows v = j+16s (s=0..4): 5 dots of 20
// = 100 FFMA/step, full 32-lane utilization. Gate/h exchange through block
// SMEM with 1-warp __syncthreads (BAR nw=1 = 3 cyc). No cross-warp coupling:
// 14 independent warps per SM, fully dephased. Grid 2048 @ 14 blocks/SM =
// single wave.

#define TSTEPS 2048
#define BATCH  4096
#define H      20
#define CHUNK  64
#define NBLK   (BATCH / 2)   // 2048 one-warp blocks

// Unified activation: cc=-1,p=1 -> sigmoid(x); cc=-2,p=2 -> tanh(x).
// sigmoid: r = 1/(1+e^-x), z = r.  tanh: r = 1/(1+e^-2x), z = 2r-1.
__device__ __forceinline__ float act(float x, float cc, float p) {
    float r = __fdividef(1.0f, 1.0f + __expf(cc * x));
    return fmaf(p, r - 1.0f, 1.0f);
}
__device__ __forceinline__ float tanh_f(float x) {
    float r = __fdividef(1.0f, 1.0f + __expf(-2.0f * x));
    return fmaf(2.0f, r - 1.0f, 1.0f);
}

__global__ void __launch_bounds__(32, 14)
lstm_warp_kernel(const float* __restrict__ u,     // [T, B, 1]
                 const float* __restrict__ Wih,   // [80, 1]
                 const float* __restrict__ Whh,   // [80, 20]
                 const float* __restrict__ Wout,  // [1, 20]
                 float* __restrict__ out)         // [T, B, 1]
{
    __shared__ __align__(16) float h_sh[2][H];     // hidden state per batch-half
    __shared__ float g_sh[2][4 * H];               // activated gates per batch-half
    __shared__ float u_sh[CHUNK][2];
    __shared__ float y_sh[CHUNK][2];

    const int lane = threadIdx.x;
    const int half = lane >> 4;      // which of the 2 batches
    const int j    = lane & 15;      // 0..15
    const int b0   = blockIdx.x * 2;

    // 5 gate rows per lane: v = j + 16*s  (v in 0..79; PyTorch order i,f,g,o)
    float w[5][H];
    float wihr[5], cc2[5], pp[5];
#pragma unroll
    for (int s = 0; s < 5; s++) {
        const int v = j + 16 * s;
        wihr[s] = Wih[v];
        const bool is_t = (v >= 2 * H) && (v < 3 * H);   // g-gate rows -> tanh
        cc2[s] = is_t ? -2.0f : -1.0f;
        pp[s]  = is_t ?  2.0f :  1.0f;
#pragma unroll
        for (int jj = 0; jj < H; jj++)
            w[s][jj] = Whh[v * H + jj];
    }
    // Owned hidden indices: k0 = j; k1 = j+16 (valid only for j<4, clamped).
    const int  k1    = (j < 4) ? (j + 16) : j;
    const float wout0 = Wout[j];
    const float wout1 = (j < 4) ? Wout[j + 16] : 0.0f;

    h_sh[half][j] = 0.0f;
    if (j < 4) h_sh[half][j + 16] = 0.0f;
    float c0 = 0.0f, c1 = 0.0f;
    __syncthreads();

#pragma unroll 1
    for (int tc = 0; tc < TSTEPS / CHUNK; tc++) {
        // Flush y of previous chunk, stage u of this chunk.
        if (tc > 0) {
            const int t0p = (tc - 1) * CHUNK;
#pragma unroll 1
            for (int e = lane; e < CHUNK * 2; e += 32) {
                const int r = e >> 1, cc = e & 1;
                out[(t0p + r) * BATCH + b0 + cc] = y_sh[r][cc];
            }
        }
        {
            const int t0 = tc * CHUNK;
#pragma unroll 1
            for (int e = lane; e < CHUNK * 2; e += 32) {
                const int r = e >> 1, cc = e & 1;
                u_sh[r][cc] = u[(t0 + r) * BATCH + b0 + cc];
            }
        }
        __syncthreads();

#pragma unroll 1
        for (int tt = 0; tt < CHUNK; tt++) {
            // ---- Phase 1: gate preactivations (5 dots of 20) ----
            const float x = u_sh[tt][half];
            float a0 = x * wihr[0], a1 = x * wihr[1], a2 = x * wihr[2],
                  a3 = x * wihr[3], a4 = x * wihr[4];
#pragma unroll
            for (int q = 0; q < H / 4; q++) {
                const float4 hq = *reinterpret_cast<const float4*>(&h_sh[half][4 * q]);
                a0 = fmaf(hq.x, w[0][4 * q + 0], a0);
                a1 = fmaf(hq.x, w[1][4 * q + 0], a1);
                a2 = fmaf(hq.x, w[2][4 * q + 0], a2);
                a3 = fmaf(hq.x, w[3][4 * q + 0], a3);
                a4 = fmaf(hq.x, w[4][4 * q + 0], a4);
                a0 = fmaf(hq.y, w[0][4 * q + 1], a0);
                a1 = fmaf(hq.y, w[1][4 * q + 1], a1);
                a2 = fmaf(hq.y, w[2][4 * q + 1], a2);
                a3 = fmaf(hq.y, w[3][4 * q + 1], a3);
                a4 = fmaf(hq.y, w[4][4 * q + 1], a4);
                a0 = fmaf(hq.z, w[0][4 * q + 2], a0);
                a1 = fmaf(hq.z, w[1][4 * q + 2], a1);
                a2 = fmaf(hq.z, w[2][4 * q + 2], a2);
                a3 = fmaf(hq.z, w[3][4 * q + 2], a3);
                a4 = fmaf(hq.z, w[4][4 * q + 2], a4);
                a0 = fmaf(hq.w, w[0][4 * q + 3], a0);
                a1 = fmaf(hq.w, w[1][4 * q + 3], a1);
                a2 = fmaf(hq.w, w[2][4 * q + 3], a2);
                a3 = fmaf(hq.w, w[3][4 * q + 3], a3);
                a4 = fmaf(hq.w, w[4][4 * q + 3], a4);
            }
            // Activated gates to SMEM (conflict-free stride-1 stores).
            g_sh[half][j + 16 * 0] = act(a0, cc2[0], pp[0]);
            g_sh[half][j + 16 * 1] = act(a1, cc2[1], pp[1]);
            g_sh[half][j + 16 * 2] = act(a2, cc2[2], pp[2]);
            g_sh[half][j + 16 * 3] = act(a3, cc2[3], pp[3]);
            g_sh[half][j + 16 * 4] = act(a4, cc2[4], pp[4]);
            __syncthreads();   // 1-warp barrier: 3 cyc

            // ---- Phase 2: c/h update for owned k's ----
            const float i0 = g_sh[half][j];
            const float f0 = g_sh[half][H + j];
            const float g0 = g_sh[half][2 * H + j];
            const float o0 = g_sh[half][3 * H + j];
            const float i1 = g_sh[half][k1];
            const float f1 = g_sh[half][H + k1];
            const float g1 = g_sh[half][2 * H + k1];
            const float o1 = g_sh[half][3 * H + k1];

            c0 = fmaf(f0, c0, i0 * g0);
            const float h0 = o0 * tanh_f(c0);
            c1 = fmaf(f1, c1, i1 * g1);
            const float h1 = o1 * tanh_f(c1);

            h_sh[half][j] = h0;
            if (j < 4) h_sh[half][k1] = h1;

            // ---- y_t = h . w_out : butterfly reduce over 16 lanes ----
            float yp = fmaf(h0, wout0, h1 * wout1);
            yp += __shfl_xor_sync(0xffffffffu, yp, 1);
            yp += __shfl_xor_sync(0xffffffffu, yp, 2);
            yp += __shfl_xor_sync(0xffffffffu, yp, 4);
            yp += __shfl_xor_sync(0xffffffffu, yp, 8);
            if (j == 0) y_sh[tt][half] = yp;
            __syncthreads();   // h/gate buffers safe for next step
        }
    }

    // Final chunk flush
    {
        const int t0p = (TSTEPS / CHUNK - 1) * CHUNK;
#pragma unroll 1
        for (int e = lane; e < CHUNK * 2; e += 32) {
            const int r = e >> 1, cc = e & 1;
            out[(t0p + r) * BATCH + b0 + cc] = y_sh[r][cc];
        }
    }
}

extern "C" void kernel_launch(void* const* d_in, const int* in_sizes, int n_in,
                              void* d_out, int out_size) {
    const float* u    = (const float*)d_in[0];  // [2048, 4096, 1]
    const float* Wih  = (const float*)d_in[1];  // [80, 1]
    const float* Whh  = (const float*)d_in[2];  // [80, 20]
    const float* Wout = (const float*)d_in[3];  // [1, 20]
    float* out = (float*)d_out;                 // [2048, 4096, 1]

    lstm_warp_kernel<<<NBLK, 32>>>(u, Wih, Whh, Wout, out);
}

// round 8
// speedup vs baseline: 2.4855x; 1.1325x over previous
#include <cuda_runtime.h>

// LSTM scan: T=2048, B=4096, IN_S=1, H=20, OUT_S=1, no biases.
// Round 7: R6 warp-autonomous structure + MUFU.TANH activations.
// Sigmoid rows' weights pre-scaled by 0.5 at load, so
// sigmoid(a) = fma(0.5, tanh.approx(a_scaled), 0.5)  -> MUFU.TANH + FFMA.
// g-gate rows: tanh(a) = tanh.approx(a) -> 1 MUFU. tanh(c) likewise.
// One warp = one block = 2 batch elements, 16 lanes each; lane j computes
// gate rows v = j+16s (s=0..4). 2048 blocks @ 14/SM = single wave.

#define TSTEPS 2048
#define BATCH  4096
#define H      20
#define CHUNK  64
#define NBLK   (BATCH / 2)   // 2048 one-warp blocks

__device__ __forceinline__ float tanha(float x) {
    float y;
    asm("tanh.approx.f32 %0, %1;" : "=f"(y) : "f"(x));
    return y;
}

__global__ void __launch_bounds__(32, 14)
lstm_warp_kernel(const float* __restrict__ u,     // [T, B, 1]
                 const float* __restrict__ Wih,   // [80, 1]
                 const float* __restrict__ Whh,   // [80, 20]
                 const float* __restrict__ Wout,  // [1, 20]
                 float* __restrict__ out)         // [T, B, 1]
{
    __shared__ __align__(16) float h_sh[2][H];     // hidden state per batch-half
    __shared__ float g_sh[2][4 * H];               // activated gates per batch-half
    __shared__ float u_sh[CHUNK][2];
    __shared__ float y_sh[CHUNK][2];

    const int lane = threadIdx.x;
    const int half = lane >> 4;      // which of the 2 batches
    const int j    = lane & 15;      // 0..15
    const int b0   = blockIdx.x * 2;

    // 5 gate rows per lane: v = j + 16*s (v in 0..79; PyTorch order i,f,g,o).
    // Sigmoid rows (i,f,o) have weights PRE-SCALED by 0.5; activation is then
    // z = fma(p, tanh(a), q) with (p,q) = (0.5,0.5) sigmoid / (1,0) tanh.
    float w[5][H];
    float wihr[5], pp[5], qq[5];
#pragma unroll
    for (int s = 0; s < 5; s++) {
        const int v = j + 16 * s;
        const bool is_t = (v >= 2 * H) && (v < 3 * H);   // g-gate rows
        const float scale = is_t ? 1.0f : 0.5f;
        pp[s] = is_t ? 1.0f : 0.5f;
        qq[s] = is_t ? 0.0f : 0.5f;
        wihr[s] = Wih[v] * scale;
#pragma unroll
        for (int jj = 0; jj < H; jj++)
            w[s][jj] = Whh[v * H + jj] * scale;
    }
    // Owned hidden indices: k0 = j; k1 = j+16 (valid only for j<4, clamped).
    const int  k1    = (j < 4) ? (j + 16) : j;
    const float wout0 = Wout[j];
    const float wout1 = (j < 4) ? Wout[j + 16] : 0.0f;

    h_sh[half][j] = 0.0f;
    if (j < 4) h_sh[half][j + 16] = 0.0f;
    float c0 = 0.0f, c1 = 0.0f;
    __syncthreads();

#pragma unroll 1
    for (int tc = 0; tc < TSTEPS / CHUNK; tc++) {
        // Flush y of previous chunk, stage u of this chunk.
        if (tc > 0) {
            const int t0p = (tc - 1) * CHUNK;
#pragma unroll 1
            for (int e = lane; e < CHUNK * 2; e += 32) {
                const int r = e >> 1, cc = e & 1;
                out[(t0p + r) * BATCH + b0 + cc] = y_sh[r][cc];
            }
        }
        {
            const int t0 = tc * CHUNK;
#pragma unroll 1
            for (int e = lane; e < CHUNK * 2; e += 32) {
                const int r = e >> 1, cc = e & 1;
                u_sh[r][cc] = u[(t0 + r) * BATCH + b0 + cc];
            }
        }
        __syncthreads();

#pragma unroll 1
        for (int tt = 0; tt < CHUNK; tt++) {
            // ---- Phase 1: gate preactivations (5 dots of 20) ----
            const float x = u_sh[tt][half];
            float a0 = x * wihr[0], a1 = x * wihr[1], a2 = x * wihr[2],
                  a3 = x * wihr[3], a4 = x * wihr[4];
#pragma unroll
            for (int q = 0; q < H / 4; q++) {
                const float4 hq = *reinterpret_cast<const float4*>(&h_sh[half][4 * q]);
                a0 = fmaf(hq.x, w[0][4 * q + 0], a0);
                a1 = fmaf(hq.x, w[1][4 * q + 0], a1);
                a2 = fmaf(hq.x, w[2][4 * q + 0], a2);
                a3 = fmaf(hq.x, w[3][4 * q + 0], a3);
                a4 = fmaf(hq.x, w[4][4 * q + 0], a4);
                a0 = fmaf(hq.y, w[0][4 * q + 1], a0);
                a1 = fmaf(hq.y, w[1][4 * q + 1], a1);
                a2 = fmaf(hq.y, w[2][4 * q + 1], a2);
                a3 = fmaf(hq.y, w[3][4 * q + 1], a3);
                a4 = fmaf(hq.y, w[4][4 * q + 1], a4);
                a0 = fmaf(hq.z, w[0][4 * q + 2], a0);
                a1 = fmaf(hq.z, w[1][4 * q + 2], a1);
                a2 = fmaf(hq.z, w[2][4 * q + 2], a2);
                a3 = fmaf(hq.z, w[3][4 * q + 2], a3);
                a4 = fmaf(hq.z, w[4][4 * q + 2], a4);
                a0 = fmaf(hq.w, w[0][4 * q + 3], a0);
                a1 = fmaf(hq.w, w[1][4 * q + 3], a1);
                a2 = fmaf(hq.w, w[2][4 * q + 3], a2);
                a3 = fmaf(hq.w, w[3][4 * q + 3], a3);
                a4 = fmaf(hq.w, w[4][4 * q + 3], a4);
            }
            // Activated gates: MUFU.TANH + FFMA each.
            g_sh[half][j + 16 * 0] = fmaf(pp[0], tanha(a0), qq[0]);
            g_sh[half][j + 16 * 1] = fmaf(pp[1], tanha(a1), qq[1]);
            g_sh[half][j + 16 * 2] = fmaf(pp[2], tanha(a2), qq[2]);
            g_sh[half][j + 16 * 3] = fmaf(pp[3], tanha(a3), qq[3]);
            g_sh[half][j + 16 * 4] = fmaf(pp[4], tanha(a4), qq[4]);
            __syncthreads();   // 1-warp barrier: 3 cyc

            // ---- Phase 2: c/h update for owned k's ----
            const float i0 = g_sh[half][j];
            const float f0 = g_sh[half][H + j];
            const float g0 = g_sh[half][2 * H + j];
            const float o0 = g_sh[half][3 * H + j];
            const float i1 = g_sh[half][k1];
            const float f1 = g_sh[half][H + k1];
            const float g1 = g_sh[half][2 * H + k1];
            const float o1 = g_sh[half][3 * H + k1];

            c0 = fmaf(f0, c0, i0 * g0);
            const float h0 = o0 * tanha(c0);
            c1 = fmaf(f1, c1, i1 * g1);
            const float h1 = o1 * tanha(c1);

            h_sh[half][j] = h0;
            if (j < 4) h_sh[half][k1] = h1;

            // ---- y_t = h . w_out : butterfly reduce over 16 lanes ----
            float yp = fmaf(h0, wout0, h1 * wout1);
            yp += __shfl_xor_sync(0xffffffffu, yp, 1);
            yp += __shfl_xor_sync(0xffffffffu, yp, 2);
            yp += __shfl_xor_sync(0xffffffffu, yp, 4);
            yp += __shfl_xor_sync(0xffffffffu, yp, 8);
            if (j == 0) y_sh[tt][half] = yp;
            __syncthreads();   // h/gate buffers safe for next step
        }
    }

    // Final chunk flush
    {
        const int t0p = (TSTEPS / CHUNK - 1) * CHUNK;
#pragma unroll 1
        for (int e = lane; e < CHUNK * 2; e += 32) {
            const int r = e >> 1, cc = e & 1;
            out[(t0p + r) * BATCH + b0 + cc] = y_sh[r][cc];
        }
    }
}

extern "C" void kernel_launch(void* const* d_in, const int* in_sizes, int n_in,
                              void* d_out, int out_size) {
    const float* u    = (const float*)d_in[0];  // [2048, 4096, 1]
    const float* Wih  = (const float*)d_in[1];  // [80, 1]
    const float* Whh  = (const float*)d_in[2];  // [80, 20]
    const float* Wout = (const float*)d_in[3];  // [1, 20]
    float* out = (float*)d_out;                 // [2048, 4096, 1]

    lstm_warp_kernel<<<NBLK, 32>>>(u, Wih, Whh, Wout, out);
}

// round 10
// speedup vs baseline: 2.6561x; 1.0686x over previous
#include <cuda_runtime.h>

// LSTM scan: T=2048, B=4096, IN_S=1, H=20, OUT_S=1, no biases.
// Round 9: R8 with the OOB split-accumulator bug fixed. 5 h-quads are
// processed as 2 pairs (quads 0/1, 2/3) + tail quad 4 -> chains 8/12 deep
// instead of 20. Deferred y-reduction (1 STS/step, per-chunk flush sums),
// MUFU.TANH activations with 0.5-prescaled sigmoid weights, one warp = one
// block = 2 batch elements, 2048 blocks @ 14/SM = single wave.

#define TSTEPS 2048
#define BATCH  4096
#define H      20
#define CHUNK  64
#define NBLK   (BATCH / 2)   // 2048 one-warp blocks
#define YP_STRIDE 17         // 16 partials + 1 pad (conflict-free flush)

__device__ __forceinline__ float tanha(float x) {
    float y;
    asm("tanh.approx.f32 %0, %1;" : "=f"(y) : "f"(x));
    return y;
}

__global__ void __launch_bounds__(32, 14)
lstm_warp_kernel(const float* __restrict__ u,     // [T, B, 1]
                 const float* __restrict__ Wih,   // [80, 1]
                 const float* __restrict__ Whh,   // [80, 20]
                 const float* __restrict__ Wout,  // [1, 20]
                 float* __restrict__ out)         // [T, B, 1]
{
    __shared__ __align__(16) float h_sh[2][H];     // hidden state per batch-half
    __shared__ float g_sh[2][4 * H];               // activated gates
    __shared__ float u_sh[CHUNK][2];
    __shared__ float y_part[CHUNK * 2 * YP_STRIDE]; // per-lane y partials

    const int lane = threadIdx.x;
    const int half = lane >> 4;      // which of the 2 batches
    const int j    = lane & 15;      // 0..15
    const int b0   = blockIdx.x * 2;

    // 5 gate rows per lane: v = j + 16*s (PyTorch order i,f,g,o).
    // Sigmoid rows prescaled by 0.5: z = fma(p, tanh(a), q),
    // (p,q) = (0.5,0.5) sigmoid / (1,0) tanh.
    float w[5][H];
    float wihr[5], pp[5], qq[5];
#pragma unroll
    for (int s = 0; s < 5; s++) {
        const int v = j + 16 * s;
        const bool is_t = (v >= 2 * H) && (v < 3 * H);
        const float scale = is_t ? 1.0f : 0.5f;
        pp[s] = is_t ? 1.0f : 0.5f;
        qq[s] = is_t ? 0.0f : 0.5f;
        wihr[s] = Wih[v] * scale;
#pragma unroll
        for (int jj = 0; jj < H; jj++)
            w[s][jj] = Whh[v * H + jj] * scale;
    }
    const int  k1    = (j < 4) ? (j + 16) : j;
    const float wout0 = Wout[j];
    const float wout1 = (j < 4) ? Wout[j + 16] : 0.0f;

    h_sh[half][j] = 0.0f;
    if (j < 4) h_sh[half][j + 16] = 0.0f;
    float c0 = 0.0f, c1 = 0.0f;
    __syncthreads();

#pragma unroll 1
    for (int tc = 0; tc < TSTEPS / CHUNK; tc++) {
        // Flush y of previous chunk: reduce 16 partials per output.
        if (tc > 0) {
            const int t0p = (tc - 1) * CHUNK;
#pragma unroll 1
            for (int e = lane; e < CHUNK * 2; e += 32) {
                const float* yp = &y_part[e * YP_STRIDE];
                float s0 = yp[0], s1 = yp[1];
#pragma unroll
                for (int q = 1; q < 8; q++) {
                    s0 += yp[2 * q];
                    s1 += yp[2 * q + 1];
                }
                const int r = e >> 1, cc = e & 1;
                out[(t0p + r) * BATCH + b0 + cc] = s0 + s1;
            }
        }
        // Stage u of this chunk.
        {
            const int t0 = tc * CHUNK;
#pragma unroll 1
            for (int e = lane; e < CHUNK * 2; e += 32) {
                const int r = e >> 1, cc = e & 1;
                u_sh[r][cc] = u[(t0 + r) * BATCH + b0 + cc];
            }
        }
        __syncthreads();

#pragma unroll 1
        for (int tt = 0; tt < CHUNK; tt++) {
            // ---- Phase 1: gate preactivations, split accumulators ----
            const float x = u_sh[tt][half];
            float a0 = x * wihr[0], a1 = x * wihr[1], a2 = x * wihr[2],
                  a3 = x * wihr[3], a4 = x * wihr[4];
            float b0a = 0.0f, b1a = 0.0f, b2a = 0.0f, b3a = 0.0f, b4a = 0.0f;
            // Quads 0..3 as two pairs: even quad -> a*, odd quad -> b*.
#pragma unroll
            for (int q = 0; q < 4; q += 2) {
                const float4 hq = *reinterpret_cast<const float4*>(&h_sh[half][4 * q]);
                const float4 hr = *reinterpret_cast<const float4*>(&h_sh[half][4 * q + 4]);
                a0 = fmaf(hq.x, w[0][4 * q + 0], a0);
                a1 = fmaf(hq.x, w[1][4 * q + 0], a1);
                a2 = fmaf(hq.x, w[2][4 * q + 0], a2);
                a3 = fmaf(hq.x, w[3][4 * q + 0], a3);
                a4 = fmaf(hq.x, w[4][4 * q + 0], a4);
                b0a = fmaf(hr.x, w[0][4 * q + 4], b0a);
                b1a = fmaf(hr.x, w[1][4 * q + 4], b1a);
                b2a = fmaf(hr.x, w[2][4 * q + 4], b2a);
                b3a = fmaf(hr.x, w[3][4 * q + 4], b3a);
                b4a = fmaf(hr.x, w[4][4 * q + 4], b4a);
                a0 = fmaf(hq.y, w[0][4 * q + 1], a0);
                a1 = fmaf(hq.y, w[1][4 * q + 1], a1);
                a2 = fmaf(hq.y, w[2][4 * q + 1], a2);
                a3 = fmaf(hq.y, w[3][4 * q + 1], a3);
                a4 = fmaf(hq.y, w[4][4 * q + 1], a4);
                b0a = fmaf(hr.y, w[0][4 * q + 5], b0a);
                b1a = fmaf(hr.y, w[1][4 * q + 5], b1a);
                b2a = fmaf(hr.y, w[2][4 * q + 5], b2a);
                b3a = fmaf(hr.y, w[3][4 * q + 5], b3a);
                b4a = fmaf(hr.y, w[4][4 * q + 5], b4a);
                a0 = fmaf(hq.z, w[0][4 * q + 2], a0);
                a1 = fmaf(hq.z, w[1][4 * q + 2], a1);
                a2 = fmaf(hq.z, w[2][4 * q + 2], a2);
                a3 = fmaf(hq.z, w[3][4 * q + 2], a3);
                a4 = fmaf(hq.z, w[4][4 * q + 2], a4);
                b0a = fmaf(hr.z, w[0][4 * q + 6], b0a);
                b1a = fmaf(hr.z, w[1][4 * q + 6], b1a);
                b2a = fmaf(hr.z, w[2][4 * q + 6], b2a);
                b3a = fmaf(hr.z, w[3][4 * q + 6], b3a);
                b4a = fmaf(hr.z, w[4][4 * q + 6], b4a);
                a0 = fmaf(hq.w, w[0][4 * q + 3], a0);
                a1 = fmaf(hq.w, w[1][4 * q + 3], a1);
                a2 = fmaf(hq.w, w[2][4 * q + 3], a2);
                a3 = fmaf(hq.w, w[3][4 * q + 3], a3);
                a4 = fmaf(hq.w, w[4][4 * q + 3], a4);
                b0a = fmaf(hr.w, w[0][4 * q + 7], b0a);
                b1a = fmaf(hr.w, w[1][4 * q + 7], b1a);
                b2a = fmaf(hr.w, w[2][4 * q + 7], b2a);
                b3a = fmaf(hr.w, w[3][4 * q + 7], b3a);
                b4a = fmaf(hr.w, w[4][4 * q + 7], b4a);
            }
            // Tail quad 4 (h[16..19]) -> b chain.
            {
                const float4 hq = *reinterpret_cast<const float4*>(&h_sh[half][16]);
                b0a = fmaf(hq.x, w[0][16], b0a);
                b1a = fmaf(hq.x, w[1][16], b1a);
                b2a = fmaf(hq.x, w[2][16], b2a);
                b3a = fmaf(hq.x, w[3][16], b3a);
                b4a = fmaf(hq.x, w[4][16], b4a);
                b0a = fmaf(hq.y, w[0][17], b0a);
                b1a = fmaf(hq.y, w[1][17], b1a);
                b2a = fmaf(hq.y, w[2][17], b2a);
                b3a = fmaf(hq.y, w[3][17], b3a);
                b4a = fmaf(hq.y, w[4][17], b4a);
                b0a = fmaf(hq.z, w[0][18], b0a);
                b1a = fmaf(hq.z, w[1][18], b1a);
                b2a = fmaf(hq.z, w[2][18], b2a);
                b3a = fmaf(hq.z, w[3][18], b3a);
                b4a = fmaf(hq.z, w[4][18], b4a);
                b0a = fmaf(hq.w, w[0][19], b0a);
                b1a = fmaf(hq.w, w[1][19], b1a);
                b2a = fmaf(hq.w, w[2][19], b2a);
                b3a = fmaf(hq.w, w[3][19], b3a);
                b4a = fmaf(hq.w, w[4][19], b4a);
            }
            a0 += b0a; a1 += b1a; a2 += b2a; a3 += b3a; a4 += b4a;

            // Activated gates: MUFU.TANH + FFMA each.
            g_sh[half][j + 16 * 0] = fmaf(pp[0], tanha(a0), qq[0]);
            g_sh[half][j + 16 * 1] = fmaf(pp[1], tanha(a1), qq[1]);
            g_sh[half][j + 16 * 2] = fmaf(pp[2], tanha(a2), qq[2]);
            g_sh[half][j + 16 * 3] = fmaf(pp[3], tanha(a3), qq[3]);
            g_sh[half][j + 16 * 4] = fmaf(pp[4], tanha(a4), qq[4]);
            __syncthreads();   // 1-warp barrier: 3 cyc

            // ---- Phase 2: c/h update for owned k's ----
            const float i0 = g_sh[half][j];
            const float f0 = g_sh[half][H + j];
            const float g0 = g_sh[half][2 * H + j];
            const float o0 = g_sh[half][3 * H + j];
            const float i1 = g_sh[half][k1];
            const float f1 = g_sh[half][H + k1];
            const float g1 = g_sh[half][2 * H + k1];
            const float o1 = g_sh[half][3 * H + k1];

            c0 = fmaf(f0, c0, i0 * g0);
            const float h0 = o0 * tanha(c0);
            c1 = fmaf(f1, c1, i1 * g1);
            const float h1 = o1 * tanha(c1);

            h_sh[half][j] = h0;
            if (j < 4) h_sh[half][k1] = h1;

            // y partial: one STS, no dependent chain.
            y_part[(tt * 2 + half) * YP_STRIDE + j] = fmaf(h0, wout0, h1 * wout1);
            __syncthreads();   // h/gate buffers safe for next step
        }
    }

    // Final chunk flush
    {
        const int t0p = (TSTEPS / CHUNK - 1) * CHUNK;
#pragma unroll 1
        for (int e = lane; e < CHUNK * 2; e += 32) {
            const float* yp = &y_part[e * YP_STRIDE];
            float s0 = yp[0], s1 = yp[1];
#pragma unroll
            for (int q = 1; q < 8; q++) {
                s0 += yp[2 * q];
                s1 += yp[2 * q + 1];
            }
            const int r = e >> 1, cc = e & 1;
            out[(t0p + r) * BATCH + b0 + cc] = s0 + s1;
        }
    }
}

extern "C" void kernel_launch(void* const* d_in, const int* in_sizes, int n_in,
                              void* d_out, int out_size) {
    const float* u    = (const float*)d_in[0];  // [2048, 4096, 1]
    const float* Wih  = (const float*)d_in[1];  // [80, 1]
    const float* Whh  = (const float*)d_in[2];  // [80, 20]
    const float* Wout = (const float*)d_in[3];  // [1, 20]
    float* out = (float*)d_out;                 // [2048, 4096, 1]

    lstm_warp_kernel<<<NBLK, 32>>>(u, Wih, Whh, Wout, out);
}

// round 11
// speedup vs baseline: 2.9544x; 1.1123x over previous
#include <cuda_runtime.h>

// LSTM scan: T=2048, B=4096, IN_S=1, H=20, OUT_S=1, no biases.
// Round 10: ownership-aligned gate rows -> zero-SMEM gate exchange.
// Lane j (of 16 per batch-half) computes slots 0..3 = gates i,f,g,o of its
// OWN k0=j (phase 2 needs no communication), slot 4 = gate (j>>2) of
// k1=16+(j&3). Lanes j<4 gather k1's f,g,o via 3 shfl.idx of z4.
// ONE __syncthreads per step (h exchange only, double-buffered h_sh).
// MUFU.TANH activations with 0.5-prescaled sigmoid weights. Deferred
// y-reduction. One warp = one block = 2 batches; 2048 blocks @ 14/SM,
// single wave.

#define TSTEPS 2048
#define BATCH  4096
#define H      20
#define CHUNK  64
#define NBLK   (BATCH / 2)   // 2048 one-warp blocks
#define YP_STRIDE 17         // 16 partials + 1 pad (conflict-free flush)

__device__ __forceinline__ float tanha(float x) {
    float y;
    asm("tanh.approx.f32 %0, %1;" : "=f"(y) : "f"(x));
    return y;
}

__global__ void __launch_bounds__(32, 14)
lstm_warp_kernel(const float* __restrict__ u,     // [T, B, 1]
                 const float* __restrict__ Wih,   // [80, 1]
                 const float* __restrict__ Whh,   // [80, 20]
                 const float* __restrict__ Wout,  // [1, 20]
                 float* __restrict__ out)         // [T, B, 1]
{
    __shared__ __align__(16) float h_sh[2][2][24];  // [buf][half][padded H]
    __shared__ float u_sh[CHUNK][2];
    __shared__ float y_part[CHUNK * 2 * YP_STRIDE];

    const int lane = threadIdx.x;
    const int half = lane >> 4;      // which of the 2 batches
    const int j    = lane & 15;      // 0..15
    const int b0   = blockIdx.x * 2;
    const int base = half << 4;      // lane base of my half

    // Row assignment (PyTorch gate order i,f,g,o; row = gate*20 + k):
    //   slot s=0..3: row = s*20 + j          (gate s of k0 = j)
    //   slot 4:      row = (j>>2)*20 + 16 + (j&3)
    // Sigmoid rows (gates 0,1,3) prescaled by 0.5: z = fma(0.5,tanh(a),0.5).
    // Tanh rows (gate 2): z = tanh(a).
    float w[5][H];
    float wihr[5];
    int rows[5];
#pragma unroll
    for (int s = 0; s < 4; s++) rows[s] = s * H + j;
    rows[4] = (j >> 2) * H + 16 + (j & 3);

    const int g4 = j >> 2;                    // slot-4 gate index
    const float pp4 = (g4 == 2) ? 1.0f : 0.5f;
    const float qq4 = (g4 == 2) ? 0.0f : 0.5f;

#pragma unroll
    for (int s = 0; s < 5; s++) {
        const bool is_t = (s == 2) || (s == 4 && g4 == 2);
        const float scale = is_t ? 1.0f : 0.5f;
        wihr[s] = Wih[rows[s]] * scale;
#pragma unroll
        for (int jj = 0; jj < H; jj++)
            w[s][jj] = Whh[rows[s] * H + jj] * scale;
    }
    const float wout0 = Wout[j];
    const float wout1 = (j < 4) ? Wout[16 + j] : 0.0f;

    h_sh[0][half][j] = 0.0f;
    if (j < 4) h_sh[0][half][16 + j] = 0.0f;
    float c0 = 0.0f, c1 = 0.0f;
    int pb = 0;
    __syncthreads();

#pragma unroll 1
    for (int tc = 0; tc < TSTEPS / CHUNK; tc++) {
        // Flush y of previous chunk: reduce 16 partials per output.
        if (tc > 0) {
            const int t0p = (tc - 1) * CHUNK;
#pragma unroll 1
            for (int e = lane; e < CHUNK * 2; e += 32) {
                const float* yp = &y_part[e * YP_STRIDE];
                float s0 = yp[0], s1 = yp[1];
#pragma unroll
                for (int q = 1; q < 8; q++) {
                    s0 += yp[2 * q];
                    s1 += yp[2 * q + 1];
                }
                const int r = e >> 1, cc = e & 1;
                out[(t0p + r) * BATCH + b0 + cc] = s0 + s1;
            }
        }
        // Stage u of this chunk.
        {
            const int t0 = tc * CHUNK;
#pragma unroll 1
            for (int e = lane; e < CHUNK * 2; e += 32) {
                const int r = e >> 1, cc = e & 1;
                u_sh[r][cc] = u[(t0 + r) * BATCH + b0 + cc];
            }
        }
        __syncthreads();

#pragma unroll 1
        for (int tt = 0; tt < CHUNK; tt++) {
            // ---- Phase 1: 5 gate-row dots of length 20, split chains ----
            const float x = u_sh[tt][half];
            float a0 = x * wihr[0], a1 = x * wihr[1], a2 = x * wihr[2],
                  a3 = x * wihr[3], a4 = x * wihr[4];
            float b0a = 0.0f, b1a = 0.0f, b2a = 0.0f, b3a = 0.0f, b4a = 0.0f;
            const float* hp = &h_sh[pb][half][0];
            // Quads 0..3 as two pairs (even -> a*, odd -> b*).
#pragma unroll
            for (int q = 0; q < 4; q += 2) {
                const float4 hq = *reinterpret_cast<const float4*>(hp + 4 * q);
                const float4 hr = *reinterpret_cast<const float4*>(hp + 4 * q + 4);
                a0 = fmaf(hq.x, w[0][4 * q + 0], a0);
                a1 = fmaf(hq.x, w[1][4 * q + 0], a1);
                a2 = fmaf(hq.x, w[2][4 * q + 0], a2);
                a3 = fmaf(hq.x, w[3][4 * q + 0], a3);
                a4 = fmaf(hq.x, w[4][4 * q + 0], a4);
                b0a = fmaf(hr.x, w[0][4 * q + 4], b0a);
                b1a = fmaf(hr.x, w[1][4 * q + 4], b1a);
                b2a = fmaf(hr.x, w[2][4 * q + 4], b2a);
                b3a = fmaf(hr.x, w[3][4 * q + 4], b3a);
                b4a = fmaf(hr.x, w[4][4 * q + 4], b4a);
                a0 = fmaf(hq.y, w[0][4 * q + 1], a0);
                a1 = fmaf(hq.y, w[1][4 * q + 1], a1);
                a2 = fmaf(hq.y, w[2][4 * q + 1], a2);
                a3 = fmaf(hq.y, w[3][4 * q + 1], a3);
                a4 = fmaf(hq.y, w[4][4 * q + 1], a4);
                b0a = fmaf(hr.y, w[0][4 * q + 5], b0a);
                b1a = fmaf(hr.y, w[1][4 * q + 5], b1a);
                b2a = fmaf(hr.y, w[2][4 * q + 5], b2a);
                b3a = fmaf(hr.y, w[3][4 * q + 5], b3a);
                b4a = fmaf(hr.y, w[4][4 * q + 5], b4a);
                a0 = fmaf(hq.z, w[0][4 * q + 2], a0);
                a1 = fmaf(hq.z, w[1][4 * q + 2], a1);
                a2 = fmaf(hq.z, w[2][4 * q + 2], a2);
                a3 = fmaf(hq.z, w[3][4 * q + 2], a3);
                a4 = fmaf(hq.z, w[4][4 * q + 2], a4);
                b0a = fmaf(hr.z, w[0][4 * q + 6], b0a);
                b1a = fmaf(hr.z, w[1][4 * q + 6], b1a);
                b2a = fmaf(hr.z, w[2][4 * q + 6], b2a);
                b3a = fmaf(hr.z, w[3][4 * q + 6], b3a);
                b4a = fmaf(hr.z, w[4][4 * q + 6], b4a);
                a0 = fmaf(hq.w, w[0][4 * q + 3], a0);
                a1 = fmaf(hq.w, w[1][4 * q + 3], a1);
                a2 = fmaf(hq.w, w[2][4 * q + 3], a2);
                a3 = fmaf(hq.w, w[3][4 * q + 3], a3);
                a4 = fmaf(hq.w, w[4][4 * q + 3], a4);
                b0a = fmaf(hr.w, w[0][4 * q + 7], b0a);
                b1a = fmaf(hr.w, w[1][4 * q + 7], b1a);
                b2a = fmaf(hr.w, w[2][4 * q + 7], b2a);
                b3a = fmaf(hr.w, w[3][4 * q + 7], b3a);
                b4a = fmaf(hr.w, w[4][4 * q + 7], b4a);
            }
            // Tail quad 4 (h[16..19]) -> b chain.
            {
                const float4 hq = *reinterpret_cast<const float4*>(hp + 16);
                b0a = fmaf(hq.x, w[0][16], b0a);
                b1a = fmaf(hq.x, w[1][16], b1a);
                b2a = fmaf(hq.x, w[2][16], b2a);
                b3a = fmaf(hq.x, w[3][16], b3a);
                b4a = fmaf(hq.x, w[4][16], b4a);
                b0a = fmaf(hq.y, w[0][17], b0a);
                b1a = fmaf(hq.y, w[1][17], b1a);
                b2a = fmaf(hq.y, w[2][17], b2a);
                b3a = fmaf(hq.y, w[3][17], b3a);
                b4a = fmaf(hq.y, w[4][17], b4a);
                b0a = fmaf(hq.z, w[0][18], b0a);
                b1a = fmaf(hq.z, w[1][18], b1a);
                b2a = fmaf(hq.z, w[2][18], b2a);
                b3a = fmaf(hq.z, w[3][18], b3a);
                b4a = fmaf(hq.z, w[4][18], b4a);
                b0a = fmaf(hq.w, w[0][19], b0a);
                b1a = fmaf(hq.w, w[1][19], b1a);
                b2a = fmaf(hq.w, w[2][19], b2a);
                b3a = fmaf(hq.w, w[3][19], b3a);
                b4a = fmaf(hq.w, w[4][19], b4a);
            }
            a0 += b0a; a1 += b1a; a2 += b2a; a3 += b3a; a4 += b4a;

            // Activations. Slots 0,1,3 sigmoid (prescaled); slot 2 tanh.
            const float zi = fmaf(0.5f, tanha(a0), 0.5f);   // i of k0
            const float zf = fmaf(0.5f, tanha(a1), 0.5f);   // f of k0
            const float zg = tanha(a2);                      // g of k0
            const float zo = fmaf(0.5f, tanha(a3), 0.5f);   // o of k0
            const float z4 = fmaf(pp4, tanha(a4), qq4);     // gate g4 of 16+(j&3)

            // k1 gate gather (used by lanes j<4 only; values bounded, safe).
            const float f1v = __shfl_sync(0xffffffffu, z4, base + j + 4);
            const float g1v = __shfl_sync(0xffffffffu, z4, base + j + 8);
            const float o1v = __shfl_sync(0xffffffffu, z4, base + j + 12);

            // ---- Phase 2: own-k update, no communication for k0 ----
            c0 = fmaf(zf, c0, zi * zg);
            const float h0 = zo * tanha(c0);

            c1 = fmaf(f1v, c1, z4 * g1v);     // z4 = i of k1 for lanes j<4
            const float h1 = o1v * tanha(c1);

            float* hn = &h_sh[pb ^ 1][half][0];
            hn[j] = h0;
            if (j < 4) hn[16 + j] = h1;

            // y partial: wout1 = 0 for j>=4; h1 bounded -> contribution 0.
            y_part[(tt * 2 + half) * YP_STRIDE + j] = fmaf(h1, wout1, h0 * wout0);

            __syncthreads();   // sole per-step barrier: h exchange
            pb ^= 1;
        }
    }

    // Final chunk flush
    {
        const int t0p = (TSTEPS / CHUNK - 1) * CHUNK;
#pragma unroll 1
        for (int e = lane; e < CHUNK * 2; e += 32) {
            const float* yp = &y_part[e * YP_STRIDE];
            float s0 = yp[0], s1 = yp[1];
#pragma unroll
            for (int q = 1; q < 8; q++) {
                s0 += yp[2 * q];
                s1 += yp[2 * q + 1];
            }
            const int r = e >> 1, cc = e & 1;
            out[(t0p + r) * BATCH + b0 + cc] = s0 + s1;
        }
    }
}

extern "C" void kernel_launch(void* const* d_in, const int* in_sizes, int n_in,
                              void* d_out, int out_size) {
    const float* u    = (const float*)d_in[0];  // [2048, 4096, 1]
    const float* Wih  = (const float*)d_in[1];  // [80, 1]
    const float* Whh  = (const float*)d_in[2];  // [80, 20]
    const float* Wout = (const float*)d_in[3];  // [1, 20]
    float* out = (float*)d_out;                 // [2048, 4096, 1]

    lstm_warp_kernel<<<NBLK, 32>>>(u, Wih, Whh, Wout, out);
}

// round 12
// speedup vs baseline: 3.4774x; 1.1770x over previous
#include <cuda_runtime.h>
#include <cuda_fp16.h>

// LSTM scan: T=2048, B=4096, IN_S=1, H=20, OUT_S=1, no biases.
// Round 11: fp16 HFMA2 dot products (full-rate on FMA pipe), fp32 state.
// Weights and h_{t-1} in fp16; gates/c/activations/y in fp32. h stored in
// SMEM as a half array -> half2 reads give natural (h_2q,h_2q+1) pairs.
// Ownership-aligned rows (R10): lane j computes gates i,f,g,o of its own
// k0=j + one gate of k1=16+(j&3); k1 gates gathered via 3 shfl. ONE
// 1-warp __syncthreads per step. MUFU.TANH activations, sigmoid rows
// prescaled by 0.5. Deferred y-reduction. One warp = one block = 2 batches;
// 2048 blocks @ 14/SM, single wave.

#define TSTEPS 2048
#define BATCH  4096
#define H      20
#define CHUNK  64
#define NBLK   (BATCH / 2)   // 2048 one-warp blocks
#define YP_STRIDE 17         // 16 partials + 1 pad

__device__ __forceinline__ float tanha(float x) {
    float y;
    asm("tanh.approx.f32 %0, %1;" : "=f"(y) : "f"(x));
    return y;
}

__global__ void __launch_bounds__(32, 14)
lstm_warp_kernel(const float* __restrict__ u,     // [T, B, 1]
                 const float* __restrict__ Wih,   // [80, 1]
                 const float* __restrict__ Whh,   // [80, 20]
                 const float* __restrict__ Wout,  // [1, 20]
                 float* __restrict__ out)         // [T, B, 1]
{
    // h as half array, double buffered; 32-half (64B) stride per batch-half
    // keeps 16B alignment for vector LDS.
    __shared__ __align__(16) __half h_sh[2][2][32];
    __shared__ float u_sh[CHUNK][2];
    __shared__ float y_part[CHUNK * 2 * YP_STRIDE];

    const int lane = threadIdx.x;
    const int half_ = lane >> 4;     // which of the 2 batches
    const int j     = lane & 15;     // 0..15
    const int b0    = blockIdx.x * 2;
    const int base  = half_ << 4;    // lane base of my half

    // Row assignment (PyTorch gate order i,f,g,o; row = gate*20 + k):
    //   slot s=0..3: row = s*20 + j     (gate s of k0 = j)
    //   slot 4:      row = (j>>2)*20 + 16 + (j&3)
    // Sigmoid rows (gates 0,1,3) prescaled by 0.5 BEFORE fp16 conversion.
    int rows[5];
#pragma unroll
    for (int s = 0; s < 4; s++) rows[s] = s * H + j;
    rows[4] = (j >> 2) * H + 16 + (j & 3);

    const int g4 = j >> 2;
    const float pp4 = (g4 == 2) ? 1.0f : 0.5f;
    const float qq4 = (g4 == 2) ? 0.0f : 0.5f;

    __half2 w2[5][10];   // 50 regs: (w[2q], w[2q+1]) per slot
    float wihr[5];
#pragma unroll
    for (int s = 0; s < 5; s++) {
        const bool is_t = (s == 2) || (s == 4 && g4 == 2);
        const float scale = is_t ? 1.0f : 0.5f;
        wihr[s] = Wih[rows[s]] * scale;
#pragma unroll
        for (int q = 0; q < 10; q++) {
            w2[s][q] = __floats2half2_rn(Whh[rows[s] * H + 2 * q] * scale,
                                         Whh[rows[s] * H + 2 * q + 1] * scale);
        }
    }
    const float wout0 = Wout[j];
    const float wout1 = (j < 4) ? Wout[16 + j] : 0.0f;

    h_sh[0][half_][j] = __float2half_rn(0.0f);
    if (j < 4) h_sh[0][half_][16 + j] = __float2half_rn(0.0f);
    float c0 = 0.0f, c1 = 0.0f;
    int pb = 0;
    __syncthreads();

#pragma unroll 1
    for (int tc = 0; tc < TSTEPS / CHUNK; tc++) {
        // Flush y of previous chunk: reduce 16 partials per output.
        if (tc > 0) {
            const int t0p = (tc - 1) * CHUNK;
#pragma unroll 1
            for (int e = lane; e < CHUNK * 2; e += 32) {
                const float* yp = &y_part[e * YP_STRIDE];
                float s0 = yp[0], s1 = yp[1];
#pragma unroll
                for (int q = 1; q < 8; q++) {
                    s0 += yp[2 * q];
                    s1 += yp[2 * q + 1];
                }
                const int r = e >> 1, cc = e & 1;
                out[(t0p + r) * BATCH + b0 + cc] = s0 + s1;
            }
        }
        // Stage u of this chunk.
        {
            const int t0 = tc * CHUNK;
#pragma unroll 1
            for (int e = lane; e < CHUNK * 2; e += 32) {
                const int r = e >> 1, cc = e & 1;
                u_sh[r][cc] = u[(t0 + r) * BATCH + b0 + cc];
            }
        }
        __syncthreads();

#pragma unroll 1
        for (int tt = 0; tt < CHUNK; tt++) {
            // ---- Phase 1: load h as 10 half2 (3 vector LDS, broadcast) ----
            const __half* hp = &h_sh[pb][half_][0];
            uint4 p0 = *reinterpret_cast<const uint4*>(hp);        // q0..3
            uint4 p1 = *reinterpret_cast<const uint4*>(hp + 8);    // q4..7
            uint2 p2 = *reinterpret_cast<const uint2*>(hp + 16);   // q8..9
            __half2 hq[10];
            hq[0] = *reinterpret_cast<__half2*>(&p0.x);
            hq[1] = *reinterpret_cast<__half2*>(&p0.y);
            hq[2] = *reinterpret_cast<__half2*>(&p0.z);
            hq[3] = *reinterpret_cast<__half2*>(&p0.w);
            hq[4] = *reinterpret_cast<__half2*>(&p1.x);
            hq[5] = *reinterpret_cast<__half2*>(&p1.y);
            hq[6] = *reinterpret_cast<__half2*>(&p1.z);
            hq[7] = *reinterpret_cast<__half2*>(&p1.w);
            hq[8] = *reinterpret_cast<__half2*>(&p2.x);
            hq[9] = *reinterpret_cast<__half2*>(&p2.y);

            const float x = u_sh[tt][half_];

            // 5 slots: two 5-deep HFMA2 chains each, combined in fp32.
            float a[5];
#pragma unroll
            for (int s = 0; s < 5; s++) {
                __half2 accA = __hmul2(hq[0], w2[s][0]);
                __half2 accB = __hmul2(hq[5], w2[s][5]);
#pragma unroll
                for (int q = 1; q < 5; q++) {
                    accA = __hfma2(hq[q],     w2[s][q],     accA);
                    accB = __hfma2(hq[5 + q], w2[s][5 + q], accB);
                }
                const __half2 acc = __hadd2(accA, accB);
                a[s] = fmaf(x, wihr[s], __low2float(acc) + __high2float(acc));
            }

            // Activations. Slots 0,1,3 sigmoid (prescaled); slot 2 tanh.
            const float zi = fmaf(0.5f, tanha(a[0]), 0.5f);  // i of k0
            const float zf = fmaf(0.5f, tanha(a[1]), 0.5f);  // f of k0
            const float zg = tanha(a[2]);                    // g of k0
            const float zo = fmaf(0.5f, tanha(a[3]), 0.5f);  // o of k0
            const float z4 = fmaf(pp4, tanha(a[4]), qq4);    // gate g4 of k1

            // k1 gate gather (lanes j<4 consume; values bounded, safe).
            const float f1v = __shfl_sync(0xffffffffu, z4, base + j + 4);
            const float g1v = __shfl_sync(0xffffffffu, z4, base + j + 8);
            const float o1v = __shfl_sync(0xffffffffu, z4, base + j + 12);

            // ---- Phase 2: own-k update (fp32 state) ----
            c0 = fmaf(zf, c0, zi * zg);
            const float h0 = zo * tanha(c0);

            c1 = fmaf(f1v, c1, z4 * g1v);    // z4 = i of k1 for lanes j<4
            const float h1 = o1v * tanha(c1);

            __half* hn = &h_sh[pb ^ 1][half_][0];
            hn[j] = __float2half_rn(h0);
            if (j < 4) hn[16 + j] = __float2half_rn(h1);

            // y partial in fp32 from the exact fp32 h.
            y_part[(tt * 2 + half_) * YP_STRIDE + j] = fmaf(h1, wout1, h0 * wout0);

            __syncthreads();   // sole per-step barrier (1-warp, ~3 cyc)
            pb ^= 1;
        }
    }

    // Final chunk flush
    {
        const int t0p = (TSTEPS / CHUNK - 1) * CHUNK;
#pragma unroll 1
        for (int e = lane; e < CHUNK * 2; e += 32) {
            const float* yp = &y_part[e * YP_STRIDE];
            float s0 = yp[0], s1 = yp[1];
#pragma unroll
            for (int q = 1; q < 8; q++) {
                s0 += yp[2 * q];
                s1 += yp[2 * q + 1];
            }
            const int r = e >> 1, cc = e & 1;
            out[(t0p + r) * BATCH + b0 + cc] = s0 + s1;
        }
    }
}

extern "C" void kernel_launch(void* const* d_in, const int* in_sizes, int n_in,
                              void* d_out, int out_size) {
    const float* u    = (const float*)d_in[0];  // [2048, 4096, 1]
    const float* Wih  = (const float*)d_in[1];  // [80, 1]
    const float* Whh  = (const float*)d_in[2];  // [80, 20]
    const float* Wout = (const float*)d_in[3];  // [1, 20]
    float* out = (float*)d_out;                 // [2048, 4096, 1]

    lstm_warp_kernel<<<NBLK, 32>>>(u, Wih, Whh, Wout, out);
}

// round 13
// speedup vs baseline: 4.9187x; 1.4145x over previous
#include <cuda_runtime.h>
#include <cuda_fp16.h>
#include <cstdint>

// LSTM scan: T=2048, B=4096, IN_S=1, H=20, OUT_S=1, no biases.
// Round 12: tensor-core recurrent GEMM. One warp = one block = 8 batches.
// Per step: gates[8x80] = h_pad[8x24] x B[24x80] via 10 tiles x
// (mma.m16n8k16 + mma.m16n8k8), fp16 inputs, fp32 accumulate.
// Column permutation puts the full (i,f,g,o) quad of each (batch,k) into a
// single lane's C fragment: even tiles = (i,f), odd tiles = (g,o),
// k = 4*(T/2) + (lane%4). Zero gate exchange. u_t is folded into the MMA as
// padded A element k=20 with B row = W_ih. Sigmoid rows prescaled by 0.5
// (z = 0.5*tanh + 0.5 via MUFU.TANH). h kept in SMEM (80B stride,
// conflict-free LDSM). One 1-warp barrier per step. Grid 512 -> ~4 warps/SM
// (one per SMSP) so MUFU.TANH (the binding pipe) is fully spread.

#define TSTEPS 2048
#define BATCH  4096
#define H      20
#define MB     8             // batches per warp/block
#define CHUNK  64
#define NBLK   (BATCH / MB)  // 512 one-warp blocks

__device__ __forceinline__ float tanha(float x) {
    float y;
    asm("tanh.approx.f32 %0, %1;" : "=f"(y) : "f"(x));
    return y;
}
__device__ __forceinline__ uint32_t pack_h2(float a, float b) {
    __half2 h = __floats2half2_rn(a, b);
    return *reinterpret_cast<uint32_t*>(&h);
}

__global__ void __launch_bounds__(32)
lstm_mma_kernel(const float* __restrict__ u,     // [T, B, 1]
                const float* __restrict__ Wih,   // [80, 1]
                const float* __restrict__ Whh,   // [80, 20]
                const float* __restrict__ Wout,  // [1, 20]
                float* __restrict__ out)         // [T, B, 1]
{
    // h_sh: 16 rows (rows 8-15 stay zero; m16 fragment reads them harmlessly),
    // 40 halves per row (80B stride -> conflict-free LDSM; cols 21+ zero).
    __shared__ __align__(16) __half  h_sh[16][40];
    __shared__ __align__(8) uint32_t u2_sh[CHUNK][MB];   // (u,0) half2 per step/batch
    __shared__ float y_sh[CHUNK][MB];

    const int lane = threadIdx.x;
    const int q    = lane & 3;    // C-fragment column parity group; k-offset
    const int nl   = lane >> 2;   // 0..7: my batch row (C) and B-frag column
    const int b0   = blockIdx.x * MB;

    // ---- Static B fragments (weights), 30 regs ----
    // GEMM col n -> weight row: t=n/8, par=n&1, rn=(n&7)>>1, m=t/2, k=4m+rn,
    // gate = (t&1) ? 2+par : par  (PyTorch order i,f,g,o), wrow = gate*20+k.
    // Sigmoid rows (gate != 2) prescaled by 0.5.
    uint32_t B0[10], B1[10], B2[10];
#pragma unroll
    for (int t = 0; t < 10; t++) {
        const int n   = 8 * t + nl;
        const int par = n & 1;
        const int rn  = (n & 7) >> 1;
        const int k   = 4 * (t >> 1) + rn;
        const int gate = (t & 1) ? (2 + par) : par;
        const int wrow = gate * H + k;
        const float s = (gate == 2) ? 1.0f : 0.5f;
        B0[t] = pack_h2(s * Whh[wrow * H + 2 * q],     s * Whh[wrow * H + 2 * q + 1]);
        B1[t] = pack_h2(s * Whh[wrow * H + 2 * q + 8], s * Whh[wrow * H + 2 * q + 9]);
        if (q < 2)       B2[t] = pack_h2(s * Whh[wrow * H + 16 + 2 * q],
                                         s * Whh[wrow * H + 17 + 2 * q]);
        else if (q == 2) B2[t] = pack_h2(s * Wih[wrow], 0.0f);
        else             B2[t] = 0u;
    }
    // My owned states: (batch nl, k = 4m+q), m=0..4.
    float wout[5];
#pragma unroll
    for (int m = 0; m < 5; m++) wout[m] = Wout[4 * m + q];

    // Zero h_sh (rows 8-15 and pad cols stay zero forever).
    {
        uint32_t* hz = reinterpret_cast<uint32_t*>(&h_sh[0][0]);
        for (int i = lane; i < 16 * 40 / 2; i += 32) hz[i] = 0u;
    }
    float cst[5] = {0.f, 0.f, 0.f, 0.f, 0.f};
    __syncthreads();

    // LDSM source address (chunk0: h cols 0-15).
    const uint32_t h_base = (uint32_t)__cvta_generic_to_shared(&h_sh[0][0]);
    const uint32_t ldsm_addr = h_base + (uint32_t)((lane & 15) * 80 + ((lane & 16) ? 16 : 0));
    // Chunk1 A element (cols 16+2q): q<2 -> h16..19; q==2 -> (u,0); q==3 -> zeros.
    const uint32_t u2_base = (uint32_t)__cvta_generic_to_shared(&u2_sh[0][0]);
    const uint32_t a2_static = (q == 2) ? (u2_base + (uint32_t)(nl * 4))
                                        : (h_base + (uint32_t)(nl * 80 + ((q == 3) ? 44 : 32 + 4 * q)));
    const uint32_t a2_step = (q == 2) ? (uint32_t)(MB * 4) : 0u;

    __half* const hrow = &h_sh[nl][0];
    const float zc = 0.0f;

#pragma unroll 1
    for (int tc = 0; tc < TSTEPS / CHUNK; tc++) {
        // Flush y of previous chunk.
        if (tc > 0) {
            const int t0p = (tc - 1) * CHUNK;
#pragma unroll 1
            for (int e = lane; e < CHUNK * MB; e += 32) {
                const int rr = e >> 3, row = e & 7;
                out[(t0p + rr) * BATCH + b0 + row] = y_sh[rr][row];
            }
        }
        // Stage (u,0) half2 per step/batch.
        {
            const float* uc = u + tc * CHUNK * BATCH + b0;
#pragma unroll 1
            for (int e = lane; e < CHUNK * MB; e += 32) {
                const int rr = e >> 3, row = e & 7;
                u2_sh[rr][row] = pack_h2(uc[rr * BATCH + row], 0.0f);
            }
        }
        __syncthreads();

#pragma unroll 1
        for (int tt = 0; tt < CHUNK; tt++) {
            // ---- A fragments ----
            uint32_t A0, A1, A2, A3;
            asm volatile("ldmatrix.sync.aligned.m8n8.x4.shared.b16 {%0,%1,%2,%3}, [%4];\n"
                         : "=r"(A0), "=r"(A1), "=r"(A2), "=r"(A3) : "r"(ldsm_addr));
            uint32_t Aa;
            asm volatile("ld.shared.b32 %0, [%1];\n"
                         : "=r"(Aa) : "r"(a2_static + (uint32_t)tt * a2_step));
            const uint32_t Ab = 0u;   // rows 8-15 of chunk1: zeros

            // ---- 10 tiles x (k16 + k8) MMA, fp32 accumulate ----
            float d[10][4];
#pragma unroll
            for (int t = 0; t < 10; t++) {
                asm volatile(
                    "mma.sync.aligned.m16n8k16.row.col.f32.f16.f16.f32 "
                    "{%0,%1,%2,%3}, {%4,%5,%6,%7}, {%8,%9}, {%10,%11,%12,%13};\n"
                    : "=f"(d[t][0]), "=f"(d[t][1]), "=f"(d[t][2]), "=f"(d[t][3])
                    : "r"(A0), "r"(A1), "r"(A2), "r"(A3),
                      "r"(B0[t]), "r"(B1[t]),
                      "f"(zc), "f"(zc), "f"(zc), "f"(zc));
                asm volatile(
                    "mma.sync.aligned.m16n8k8.row.col.f32.f16.f16.f32 "
                    "{%0,%1,%2,%3}, {%4,%5}, {%6}, {%0,%1,%2,%3};\n"
                    : "+f"(d[t][0]), "+f"(d[t][1]), "+f"(d[t][2]), "+f"(d[t][3])
                    : "r"(Aa), "r"(Ab), "r"(B2[t]));
            }

            // ---- Activations + state update (all in-lane) ----
            // Tile 2m: c0 = i (sigmoid), c1 = f (sigmoid);
            // Tile 2m+1: c0 = g (tanh), c1 = o (sigmoid). k = 4m + q, batch nl.
            float yp = 0.0f;
#pragma unroll
            for (int m = 0; m < 5; m++) {
                const float zi = fmaf(0.5f, tanha(d[2 * m][0]), 0.5f);
                const float zf = fmaf(0.5f, tanha(d[2 * m][1]), 0.5f);
                const float zg = tanha(d[2 * m + 1][0]);
                const float zo = fmaf(0.5f, tanha(d[2 * m + 1][1]), 0.5f);
                cst[m] = fmaf(zf, cst[m], zi * zg);
                const float h = zo * tanha(cst[m]);
                yp = fmaf(h, wout[m], yp);
                hrow[4 * m + q] = __float2half_rn(h);
            }

            // y reduce over the 4 lanes of my batch row.
            yp += __shfl_xor_sync(0xffffffffu, yp, 1);
            yp += __shfl_xor_sync(0xffffffffu, yp, 2);
            if (q == 0) y_sh[tt][nl] = yp;

            __syncthreads();   // 1-warp barrier: h_t visible for next LDSM
        }
    }

    // Final chunk flush.
    {
        const int t0p = (TSTEPS / CHUNK - 1) * CHUNK;
#pragma unroll 1
        for (int e = lane; e < CHUNK * MB; e += 32) {
            const int rr = e >> 3, row = e & 7;
            out[(t0p + rr) * BATCH + b0 + row] = y_sh[rr][row];
        }
    }
}

extern "C" void kernel_launch(void* const* d_in, const int* in_sizes, int n_in,
                              void* d_out, int out_size) {
    const float* u    = (const float*)d_in[0];  // [2048, 4096, 1]
    const float* Wih  = (const float*)d_in[1];  // [80, 1]
    const float* Whh  = (const float*)d_in[2];  // [80, 20]
    const float* Wout = (const float*)d_in[3];  // [1, 20]
    float* out = (float*)d_out;                 // [2048, 4096, 1]

    lstm_mma_kernel<<<NBLK, 32>>>(u, Wih, Whh, Wout, out);
}